// round 6
// baseline (speedup 1.0000x reference)
#include <cuda_runtime.h>

// out[i] = cos(x[i]) (analytical collapse of the 4-wire RY/RZ/CNOT circuit;
// weights provably unused: diagonal unit phases don't change probabilities and
// the CNOT-chain permutation satisfies T^4 = I).
//
// R6: probe high per-warp MLP / small grid: ILP=4 float4 per thread
// (front-batched LDG.128 x4, MLP_p1=4), 256 blocks x 256 threads. All prior
// variants (ILP1/2, TMA, stcs) sit at the ~5000-cycle T_ovh launch floor; this
// tests whether fewer CTAs + deeper per-warp MLP shaves the distribution ramp.

__global__ void __launch_bounds__(256) qk_cos6(const float4* __restrict__ x,
                                               float4* __restrict__ out, int n4) {
    int i = (blockIdx.x * blockDim.x + threadIdx.x) * 4;
    if (i + 3 < n4) {
        // front-batch all four 128-bit loads
        float4 v0 = x[i];
        float4 v1 = x[i + 1];
        float4 v2 = x[i + 2];
        float4 v3 = x[i + 3];
        float4 r0, r1, r2, r3;
        r0.x = __cosf(v0.x); r0.y = __cosf(v0.y); r0.z = __cosf(v0.z); r0.w = __cosf(v0.w);
        r1.x = __cosf(v1.x); r1.y = __cosf(v1.y); r1.z = __cosf(v1.z); r1.w = __cosf(v1.w);
        r2.x = __cosf(v2.x); r2.y = __cosf(v2.y); r2.z = __cosf(v2.z); r2.w = __cosf(v2.w);
        r3.x = __cosf(v3.x); r3.y = __cosf(v3.y); r3.z = __cosf(v3.z); r3.w = __cosf(v3.w);
        __stcs(&out[i],     r0);
        __stcs(&out[i + 1], r1);
        __stcs(&out[i + 2], r2);
        __stcs(&out[i + 3], r3);
    } else {
#pragma unroll
        for (int k = 0; k < 4; k++) {
            int j = i + k;
            if (j < n4) {
                float4 v = x[j];
                float4 r;
                r.x = __cosf(v.x); r.y = __cosf(v.y);
                r.z = __cosf(v.z); r.w = __cosf(v.w);
                __stcs(&out[j], r);
            }
        }
    }
}

__global__ void qk_cos_tail(const float* __restrict__ x, float* __restrict__ out,
                            int start, int n) {
    int i = start + blockIdx.x * blockDim.x + threadIdx.x;
    if (i < n) out[i] = __cosf(x[i]);
}

extern "C" void kernel_launch(void* const* d_in, const int* in_sizes, int n_in,
                              void* d_out, int out_size) {
    const float* x = (const float*)d_in[0];   // (262144, 4) float32
    float* out = (float*)d_out;
    int n = out_size;          // 1048576
    int n4 = n >> 2;           // 262144 float4s

    const int T = 256;
    int threads_needed = (n4 + 3) >> 2;        // ILP=4
    int blocks = (threads_needed + T - 1) / T; // 256 for this shape
    qk_cos6<<<blocks, T>>>((const float4*)x, (float4*)out, n4);

    int rem = n - (n4 << 2);
    if (rem > 0) qk_cos_tail<<<1, 32>>>(x, out, n4 << 2, n);
}